// round 7
// baseline (speedup 1.0000x reference)
#include <cuda_runtime.h>
#include <cstdint>
#include <math.h>

#define TSTEPS 4096
#define DIN    512
#define FDIM   256
#define HID    200
#define G4     800
#define KDIM   40
#define NSLOT  128
#define EPSF   1e-12f
#define CLSZ   8

// ---------------- scratch (device globals) ----------------
__device__ float g_xs[TSTEPS * FDIM];
__device__ float g_gx[TSTEPS * G4];
__device__ float g_WinT[FDIM * DIN];
__device__ float g_Wx[G4 * FDIM];
__device__ float g_wy[G4];
__device__ float g_bsum[G4];

// ---------------- helpers ----------------
__device__ __forceinline__ float fsigmoid(float x) {
    return __fdividef(1.f, 1.f + __expf(-x));
}
__device__ __forceinline__ float ftanh(float x) {
    float a = fabsf(x);
    float e = __expf(-2.f * a);
    float r = __fdividef(1.f - e, 1.f + e);
    return copysignf(r, x);
}
__device__ __forceinline__ uint32_t smem_u32(const void* p) {
    return (uint32_t)__cvta_generic_to_shared(p);
}
__device__ __forceinline__ uint32_t my_cluster_rank() {
    uint32_t r; asm("mov.u32 %0, %%cluster_ctarank;" : "=r"(r)); return r;
}
__device__ __forceinline__ uint32_t mapa_u32(uint32_t laddr, uint32_t rank) {
    uint32_t r;
    asm("mapa.shared::cluster.u32 %0, %1, %2;" : "=r"(r) : "r"(laddr), "r"(rank));
    return r;
}
__device__ __forceinline__ void cluster_sync_() {
    asm volatile("barrier.cluster.arrive.aligned;" ::: "memory");
    asm volatile("barrier.cluster.wait.aligned;" ::: "memory");
}
__device__ __forceinline__ void dsmem_st_f32(uint32_t raddr, float v) {
    asm volatile("st.shared::cluster.f32 [%0], %1;" :: "r"(raddr), "f"(v) : "memory");
}
// release store of a flag counter into a (possibly remote) CTA's smem
__device__ __forceinline__ void st_release_u32(uint32_t raddr, unsigned v) {
    asm volatile("st.release.cluster.shared::cluster.u32 [%0], %1;"
                 :: "r"(raddr), "r"(v) : "memory");
}
// acquire load of a flag counter from local smem
__device__ __forceinline__ unsigned ld_acquire_u32(uint32_t addr) {
    unsigned v;
    asm volatile("ld.acquire.cluster.shared::cta.u32 %0, [%1];"
                 : "=r"(v) : "r"(addr) : "memory");
    return v;
}
// spin until min(pflag[0..6]) >= t
__device__ __forceinline__ void wait_pflags_ge(uint32_t baseA, unsigned t) {
    for (;;) {
        unsigned mn = 0xffffffffu;
#pragma unroll
        for (int p = 0; p < 7; p++) mn = min(mn, ld_acquire_u32(baseA + 4u * (unsigned)p));
        if (mn >= t) break;
    }
}
// packed fp32x2 FMA: d = a*b + d  (sm_100 FFMA2; ptxas never auto-fuses this)
__device__ __forceinline__ void fma2(unsigned long long& d, unsigned long long a, unsigned long long b) {
    asm("fma.rn.f32x2 %0, %1, %2, %0;" : "+l"(d) : "l"(a), "l"(b));
}
__device__ __forceinline__ float2 unpack2(unsigned long long v) {
    float2 r; asm("mov.b64 {%0, %1}, %2;" : "=f"(r.x), "=f"(r.y) : "l"(v)); return r;
}
__device__ __forceinline__ unsigned long long pack2(float x, float y) {
    unsigned long long v; asm("mov.b64 %0, {%1, %2};" : "=l"(v) : "f"(x), "f"(y)); return v;
}

// ---------------- prep ----------------
__global__ void prep_kernel(const float* __restrict__ W_in, const float* __restrict__ W_ih,
                            const float* __restrict__ b_ih, const float* __restrict__ b_hh) {
    int idx = blockIdx.x * blockDim.x + threadIdx.x;
    if (idx < G4 * FDIM) {
        int n = idx / FDIM, k = idx % FDIM;
        g_Wx[idx] = W_ih[n * (FDIM + 1) + k];
    }
    if (idx < DIN * FDIM) {
        int k = idx / FDIM, n = idx % FDIM;
        g_WinT[n * DIN + k] = W_in[idx];
    }
    if (idx < G4) {
        g_wy[idx]   = W_ih[idx * (FDIM + 1) + FDIM];
        g_bsum[idx] = b_ih[idx] + b_hh[idx];
    }
}

// ---------------- GEMM C = A * B^T ----------------
__device__ __forceinline__ void gemm_nt_body(
    const float* __restrict__ A, const float* __restrict__ B, float* __restrict__ C,
    int M, int N, int K,
    const float* __restrict__ bias, const float* __restrict__ yvec, const float* __restrict__ wy)
{
    __shared__ __align__(16) float As[16][64];
    __shared__ __align__(16) float Bs[16][64];
    const int m0 = blockIdx.y * 64, n0 = blockIdx.x * 64;
    const int tid = threadIdx.x;
    const int tx = tid % 16, ty = tid / 16;
    const int lr = tid / 4, lc4 = (tid % 4) * 4;

    float acc[4][4];
#pragma unroll
    for (int i = 0; i < 4; i++)
#pragma unroll
        for (int j = 0; j < 4; j++) acc[i][j] = 0.f;

    for (int k0 = 0; k0 < K; k0 += 16) {
        float4 av = *reinterpret_cast<const float4*>(A + (size_t)(m0 + lr) * K + k0 + lc4);
        As[lc4 + 0][lr] = av.x; As[lc4 + 1][lr] = av.y;
        As[lc4 + 2][lr] = av.z; As[lc4 + 3][lr] = av.w;
        float4 bv = make_float4(0.f, 0.f, 0.f, 0.f);
        if (n0 + lr < N) bv = *reinterpret_cast<const float4*>(B + (size_t)(n0 + lr) * K + k0 + lc4);
        Bs[lc4 + 0][lr] = bv.x; Bs[lc4 + 1][lr] = bv.y;
        Bs[lc4 + 2][lr] = bv.z; Bs[lc4 + 3][lr] = bv.w;
        __syncthreads();
#pragma unroll
        for (int kk = 0; kk < 16; kk++) {
            float4 a4 = *reinterpret_cast<const float4*>(&As[kk][ty * 4]);
            float4 b4 = *reinterpret_cast<const float4*>(&Bs[kk][tx * 4]);
            float aa[4] = {a4.x, a4.y, a4.z, a4.w};
            float bb[4] = {b4.x, b4.y, b4.z, b4.w};
#pragma unroll
            for (int i = 0; i < 4; i++)
#pragma unroll
                for (int j = 0; j < 4; j++) acc[i][j] = fmaf(aa[i], bb[j], acc[i][j]);
        }
        __syncthreads();
    }
#pragma unroll
    for (int i = 0; i < 4; i++) {
        int m = m0 + ty * 4 + i;
        float yv = 0.f;
        if (yvec) yv = (m == 0) ? 0.f : yvec[m - 1];
#pragma unroll
        for (int j = 0; j < 4; j++) {
            int n = n0 + tx * 4 + j;
            if (n < N) {
                float v = acc[i][j] + (bias ? bias[n] : 0.f);
                if (wy) v = fmaf(yv, wy[n], v);
                C[(size_t)m * N + n] = v;
            }
        }
    }
}

__global__ void __launch_bounds__(256) gemm1_kernel(const float* __restrict__ x,
                                                    const float* __restrict__ b_in) {
    gemm_nt_body(x, g_WinT, g_xs, TSTEPS, FDIM, DIN, b_in, nullptr, nullptr);
}
__global__ void __launch_bounds__(256) gemm2_kernel(const float* __restrict__ y) {
    gemm_nt_body(g_xs, g_Wx, g_gx, TSTEPS, G4, FDIM, g_bsum, y, g_wy);
}

// ---------------- fused kernel shared state ----------------
struct Shm {
    __align__(16) float h[2][HID];         // double-buffered hidden (dsmem broadcast target)
    __align__(16) float Wk[HID * KDIM];    // consumer: W_k
    __align__(8)  float Ws[HID];
    __align__(8)  float bk[KDIM];
    __align__(8)  float key[KDIM];
    __align__(8)  float kn[KDIM];
    float wsum[4];
    float sig, bs;
    __align__(16) unsigned pflag[7];       // producer r published h_{pflag[r]}
    unsigned cflag;                        // consumer finished reading h_{cflag}
};

__global__ void __cluster_dims__(CLSZ, 1, 1) __launch_bounds__(256, 1)
fused_kernel(const float* __restrict__ W_hh,
             const float* __restrict__ W_k, const float* __restrict__ b_k,
             const float* __restrict__ W_s, const float* __restrict__ b_s,
             float* __restrict__ out)
{
    __shared__ Shm S;
    const int tid = threadIdx.x;
    const uint32_t rank = my_cluster_rank();
    const bool is_consumer = (rank == CLSZ - 1);

    const uint32_t pflagA = smem_u32(&S.pflag[0]);
    const uint32_t cflagA = smem_u32(&S.cflag);
    if (tid < 7)  S.pflag[tid] = 0;
    if (tid == 7) S.cflag = 0;
    if (tid < HID) { S.h[0][tid] = 0.f; S.h[1][tid] = 0.f; }

    // remote flag handle: thread i (i<8) targets rank i's copy of MY flag slot
    uint32_t r_flag_mine = 0;
    if (tid < CLSZ) {
        uint32_t myslotA = is_consumer ? cflagA : (pflagA + 4u * rank);
        r_flag_mine = mapa_u32(myslotA, (uint32_t)tid);
    }

    // ---------- producer init ----------
    const int units = is_consumer ? 0 : ((rank < 6) ? 29 : 26);
    const int base  = 29 * (int)rank;            // rank 6 -> 174
    const int nact  = 8 * units;
    const bool act  = tid < nact;
    const int u   = tid >> 3;                    // unit within CTA
    const int sub = tid & 7;                     // 2*gate + cc
    const int g   = sub >> 1;
    const int cc  = sub & 1;
    const int grow = act ? (g * HID + base + u) : 0;

    unsigned long long w[50];
    if (act) {
        const unsigned long long* wp =
            reinterpret_cast<const unsigned long long*>(W_hh + (size_t)grow * HID + cc * 100);
#pragma unroll
        for (int q = 0; q < 50; q++) w[q] = wp[q];
    }
    unsigned mask = 0;
    if (act) {
        int rem = nact - (tid & ~31);
        mask = (rem >= 32) ? 0xffffffffu : ((1u << rem) - 1u);
    }
    uint32_t r_h[CLSZ];
    if (act && sub == 0) {
        uint32_t hA = smem_u32(&S.h[0][0]);
#pragma unroll
        for (int p = 0; p < CLSZ; p++) r_h[p] = mapa_u32(hA, (uint32_t)p);
    }

    // ---------- consumer init ----------
    unsigned long long M2[20];
    float wr = 0.f;
    if (is_consumer) {
        for (int i = tid; i < HID * KDIM; i += 256) S.Wk[i] = W_k[i];
        for (int i = tid; i < HID; i += 256) S.Ws[i] = W_s[i];
        if (tid < KDIM) S.bk[tid] = b_k[tid];
        if (tid == 0)   S.bs = b_s[0];
        if (tid < NSLOT) {
#pragma unroll
            for (int q = 0; q < 20; q++) M2[q] = pack2(1e-6f, 1e-6f);
            wr = (tid == 0) ? 1.f : 0.f;
        }
    }

    __syncthreads();
    cluster_sync_();   // flags zeroed + h zeroed everywhere before any traffic

    if (!is_consumer) {
        // ================= LSTM producer =================
        float cst = 0.f;
        float gxv = (act && cc == 0) ? g_gx[grow] : 0.f;

        for (int t = 0; t < TSTEPS; t++) {
            const int buf = t & 1, bw = buf ^ 1;
            // h_t available once every producer published step t (pflag >= t)
            if (t >= 1) wait_pflags_ge(pflagA, (unsigned)t);

            float gxn = 0.f;
            if (act && cc == 0) {
                int tn = (t + 1 < TSTEPS) ? (t + 1) : t;   // prefetch next gx
                gxn = g_gx[(size_t)tn * G4 + grow];
            }
            if (act) {
                const unsigned long long* h8 =
                    reinterpret_cast<const unsigned long long*>(&S.h[buf][cc * 100]);
                unsigned long long a0 = 0, a1 = 0, a2 = 0, a3 = 0;
#pragma unroll
                for (int q = 0; q < 48; q += 4) {
                    fma2(a0, w[q],     h8[q]);
                    fma2(a1, w[q + 1], h8[q + 1]);
                    fma2(a2, w[q + 2], h8[q + 2]);
                    fma2(a3, w[q + 3], h8[q + 3]);
                }
                fma2(a0, w[48], h8[48]);
                fma2(a1, w[49], h8[49]);
                float2 f0 = unpack2(a0), f1 = unpack2(a1), f2 = unpack2(a2), f3 = unpack2(a3);
                float dsum = ((f0.x + f0.y) + (f1.x + f1.y)) + ((f2.x + f2.y) + (f3.x + f3.y));
                dsum += __shfl_xor_sync(mask, dsum, 1);          // combine k-halves
                float av = 0.f;
                if (cc == 0) {
                    float gs = dsum + gxv;
                    av = (g == 2) ? ftanh(gs) : fsigmoid(gs);    // gate activation (even lanes)
                }
                float fv = __shfl_down_sync(mask, av, 2);
                float gv = __shfl_down_sync(mask, av, 4);
                float ov = __shfl_down_sync(mask, av, 6);
                if (sub == 0) {
                    cst = fv * cst + av * gv;
                    float h = ov * ftanh(cst);
                    // h_{t+1} overwrites h_{t-1}: consumer must be done reading it
                    if (t >= 2) { while (ld_acquire_u32(cflagA) < (unsigned)(t - 1)) {} }
                    const uint32_t off = (uint32_t)(bw * HID + base + u) * 4u;
#pragma unroll
                    for (int p = 0; p < CLSZ; p++) dsmem_st_f32(r_h[p] + off, h);
                }
            }
            gxv = gxn;
            __syncthreads();                     // all h stores issued before release
            if (tid < CLSZ) st_release_u32(r_flag_mine, (unsigned)(t + 1));
        }
        cluster_sync_();   // keep smem alive for in-flight remote ops
        return;
    }

    // ================= consumer: keys + sigma + MANN =================
    const int kk_ = tid >> 2, kp = tid & 3;      // keys mapping (tid<160)
    const int sp  = tid - 160;                   // sigma mapping (160<=tid<168)

    for (int s = 1; s <= TSTEPS; s++) {
        wait_pflags_ge(pflagA, (unsigned)s);     // h_s delivered to our smem
        const float* hb = &S.h[s & 1][0];

        // ---- keys (160 thr, 4/output) + sigma (8 thr) : the only readers of hb ----
        if (tid < 160) {
            const float* wp = &S.Wk[(kp * 50) * KDIM + kk_];
            const float* hp = &hb[kp * 50];
            float a = 0.f, b = 0.f;
#pragma unroll
            for (int i = 0; i < 50; i += 2) {
                a = fmaf(hp[i],     wp[i * KDIM],       a);
                b = fmaf(hp[i + 1], wp[(i + 1) * KDIM], b);
            }
            float acc = a + b;
            acc += __shfl_xor_sync(0xffffffffu, acc, 1);
            acc += __shfl_xor_sync(0xffffffffu, acc, 2);
            if (kp == 0) {
                float kv = ftanh(acc + S.bk[kk_]);
                S.key[kk_] = kv;
                S.kn[kk_]  = kv / fmaxf(fabsf(kv), EPSF);
            }
        } else if (tid < 168) {
            float a = 0.f;
#pragma unroll
            for (int i = 0; i < 25; i++) a = fmaf(hb[sp * 25 + i], S.Ws[sp * 25 + i], a);
            a += __shfl_xor_sync(0xFFu, a, 4);
            a += __shfl_xor_sync(0xFFu, a, 2);
            a += __shfl_xor_sync(0xFFu, a, 1);
            if (sp == 0) S.sig = fsigmoid(a + S.bs);
        }
        __syncthreads();                         // all reads of hb complete
        if (tid < CLSZ) st_release_u32(r_flag_mine, (unsigned)s);   // done with h_s

        // ---- MANN step (128 threads, one slot each) ----
        float e = 0.f;
        if (tid < NSLOT) {
            const float sg = S.sig;
            const float ww = fmaf(sg, wr, 1.f - sg);     // wlu mask == 1 identically
            const unsigned long long ww2 = pack2(ww, ww);
            const unsigned long long* k2  = reinterpret_cast<const unsigned long long*>(S.key);
            const unsigned long long* kn2 = reinterpret_cast<const unsigned long long*>(S.kn);
            unsigned long long n0 = 0, n1 = 0, d0 = 0, d1 = 0;
#pragma unroll
            for (int q = 0; q < 20; q += 2) {
                fma2(M2[q],     ww2, k2[q]);
                fma2(M2[q + 1], ww2, k2[q + 1]);
                fma2(n0, M2[q],     M2[q]);
                fma2(n1, M2[q + 1], M2[q + 1]);
                fma2(d0, M2[q],     kn2[q]);
                fma2(d1, M2[q + 1], kn2[q + 1]);
            }
            float2 na = unpack2(n0), nb = unpack2(n1), da = unpack2(d0), db = unpack2(d1);
            float ns  = (na.x + na.y) + (nb.x + nb.y);   // >= 4e-11, never 0
            float dot = (da.x + da.y) + (db.x + db.y);
            e = __expf(dot * rsqrtf(ns));                // |logit| <= sqrt(40)
            float acc = e;
#pragma unroll
            for (int off = 16; off > 0; off >>= 1) acc += __shfl_xor_sync(0xffffffffu, acc, off);
            if ((tid & 31) == 0) S.wsum[tid >> 5] = acc;
        }
        __syncthreads();
        if (tid < NSLOT) {
            float tot = (S.wsum[0] + S.wsum[1]) + (S.wsum[2] + S.wsum[3]);
            wr = __fdividef(e, tot);
        }
    }

    if (tid < NSLOT) {
#pragma unroll
        for (int q = 0; q < 20; q++) {
            float2 v = unpack2(M2[q]);
            out[tid * KDIM + 2 * q]     = v.x;
            out[tid * KDIM + 2 * q + 1] = v.y;
        }
    }
    cluster_sync_();   // keep smem alive for in-flight remote ops
}

// ---------------- launch ----------------
extern "C" void kernel_launch(void* const* d_in, const int* in_sizes, int n_in,
                              void* d_out, int out_size) {
    const float* x    = (const float*)d_in[0];
    const float* y    = (const float*)d_in[1];
    const float* W_in = (const float*)d_in[2];
    const float* b_in = (const float*)d_in[3];
    const float* W_ih = (const float*)d_in[4];
    const float* W_hh = (const float*)d_in[5];
    const float* b_ih = (const float*)d_in[6];
    const float* b_hh = (const float*)d_in[7];
    const float* W_k  = (const float*)d_in[8];
    const float* b_k  = (const float*)d_in[9];
    const float* W_s  = (const float*)d_in[10];
    const float* b_s  = (const float*)d_in[11];
    // gamma (d_in[12]) provably unused: wlu mask is identically 1, wu/gamma cancel

    prep_kernel<<<(G4 * FDIM + 255) / 256, 256>>>(W_in, W_ih, b_ih, b_hh);
    gemm1_kernel<<<dim3(FDIM / 64, TSTEPS / 64), 256>>>(x, b_in);
    gemm2_kernel<<<dim3((G4 + 63) / 64, TSTEPS / 64), 256>>>(y);
    fused_kernel<<<CLSZ, 256>>>(W_hh, W_k, b_k, W_s, b_s, (float*)d_out);
}

// round 8
// speedup vs baseline: 1.1349x; 1.1349x over previous
#include <cuda_runtime.h>
#include <cstdint>
#include <math.h>

#define TSTEPS 4096
#define DIN    512
#define FDIM   256
#define HID    200
#define G4     800
#define KDIM   40
#define NSLOT  128
#define EPSF   1e-12f
#define CLSZ   8

// ---------------- scratch (device globals) ----------------
__device__ float g_xs[TSTEPS * FDIM];
__device__ float g_gx[TSTEPS * G4];
__device__ float g_WinT[FDIM * DIN];
__device__ float g_Wx[G4 * FDIM];
__device__ float g_wy[G4];
__device__ float g_bsum[G4];

// ---------------- helpers ----------------
__device__ __forceinline__ float fsigmoid(float x) {
    return __fdividef(1.f, 1.f + __expf(-x));
}
__device__ __forceinline__ float ftanh(float x) {
    float a = fabsf(x);
    float e = __expf(-2.f * a);
    float r = __fdividef(1.f - e, 1.f + e);
    return copysignf(r, x);
}
__device__ __forceinline__ uint32_t smem_u32(const void* p) {
    return (uint32_t)__cvta_generic_to_shared(p);
}
__device__ __forceinline__ uint32_t my_cluster_rank() {
    uint32_t r; asm("mov.u32 %0, %%cluster_ctarank;" : "=r"(r)); return r;
}
__device__ __forceinline__ uint32_t mapa_u32(uint32_t laddr, uint32_t rank) {
    uint32_t r;
    asm("mapa.shared::cluster.u32 %0, %1, %2;" : "=r"(r) : "r"(laddr), "r"(rank));
    return r;
}
__device__ __forceinline__ void cluster_sync_() {
    asm volatile("barrier.cluster.arrive.aligned;" ::: "memory");
    asm volatile("barrier.cluster.wait.aligned;" ::: "memory");
}
__device__ __forceinline__ void dsmem_st_u64(uint32_t raddr, unsigned long long v) {
    asm volatile("st.shared::cluster.u64 [%0], %1;" :: "r"(raddr), "l"(v) : "memory");
}
// release store of a flag counter into a (possibly remote) CTA's smem
__device__ __forceinline__ void st_release_u32(uint32_t raddr, unsigned v) {
    asm volatile("st.release.cluster.shared::cluster.u32 [%0], %1;"
                 :: "r"(raddr), "r"(v) : "memory");
}
// acquire load of a flag counter from local smem
__device__ __forceinline__ unsigned ld_acquire_u32(uint32_t addr) {
    unsigned v;
    asm volatile("ld.acquire.cluster.shared::cta.u32 %0, [%1];"
                 : "=r"(v) : "r"(addr) : "memory");
    return v;
}
// warp-0 cooperative poll: lane p (<7) watches pflag[p]; whole warp votes
__device__ __forceinline__ void warp_poll_pflags(uint32_t baseA, unsigned t) {
    const int lane = threadIdx.x & 31;
    bool ok;
    do {
        unsigned v = 0xffffffffu;
        if (lane < 7) v = ld_acquire_u32(baseA + 4u * (unsigned)lane);
        ok = __all_sync(0xffffffffu, v >= t);
    } while (!ok);
}
// packed fp32x2 FMA: d = a*b + d  (sm_100 FFMA2; ptxas never auto-fuses this)
__device__ __forceinline__ void fma2(unsigned long long& d, unsigned long long a, unsigned long long b) {
    asm("fma.rn.f32x2 %0, %1, %2, %0;" : "+l"(d) : "l"(a), "l"(b));
}
__device__ __forceinline__ float2 unpack2(unsigned long long v) {
    float2 r; asm("mov.b64 {%0, %1}, %2;" : "=f"(r.x), "=f"(r.y) : "l"(v)); return r;
}
__device__ __forceinline__ unsigned long long pack2(float x, float y) {
    unsigned long long v; asm("mov.b64 %0, {%1, %2};" : "=l"(v) : "f"(x), "f"(y)); return v;
}

// ---------------- prep ----------------
__global__ void prep_kernel(const float* __restrict__ W_in, const float* __restrict__ W_ih,
                            const float* __restrict__ b_ih, const float* __restrict__ b_hh) {
    int idx = blockIdx.x * blockDim.x + threadIdx.x;
    if (idx < G4 * FDIM) {
        int n = idx / FDIM, k = idx % FDIM;
        g_Wx[idx] = W_ih[n * (FDIM + 1) + k];
    }
    if (idx < DIN * FDIM) {
        int k = idx / FDIM, n = idx % FDIM;
        g_WinT[n * DIN + k] = W_in[idx];
    }
    if (idx < G4) {
        g_wy[idx]   = W_ih[idx * (FDIM + 1) + FDIM];
        g_bsum[idx] = b_ih[idx] + b_hh[idx];
    }
}

// ---------------- GEMM C = A * B^T ----------------
__device__ __forceinline__ void gemm_nt_body(
    const float* __restrict__ A, const float* __restrict__ B, float* __restrict__ C,
    int M, int N, int K,
    const float* __restrict__ bias, const float* __restrict__ yvec, const float* __restrict__ wy)
{
    __shared__ __align__(16) float As[16][64];
    __shared__ __align__(16) float Bs[16][64];
    const int m0 = blockIdx.y * 64, n0 = blockIdx.x * 64;
    const int tid = threadIdx.x;
    const int tx = tid % 16, ty = tid / 16;
    const int lr = tid / 4, lc4 = (tid % 4) * 4;

    float acc[4][4];
#pragma unroll
    for (int i = 0; i < 4; i++)
#pragma unroll
        for (int j = 0; j < 4; j++) acc[i][j] = 0.f;

    for (int k0 = 0; k0 < K; k0 += 16) {
        float4 av = *reinterpret_cast<const float4*>(A + (size_t)(m0 + lr) * K + k0 + lc4);
        As[lc4 + 0][lr] = av.x; As[lc4 + 1][lr] = av.y;
        As[lc4 + 2][lr] = av.z; As[lc4 + 3][lr] = av.w;
        float4 bv = make_float4(0.f, 0.f, 0.f, 0.f);
        if (n0 + lr < N) bv = *reinterpret_cast<const float4*>(B + (size_t)(n0 + lr) * K + k0 + lc4);
        Bs[lc4 + 0][lr] = bv.x; Bs[lc4 + 1][lr] = bv.y;
        Bs[lc4 + 2][lr] = bv.z; Bs[lc4 + 3][lr] = bv.w;
        __syncthreads();
#pragma unroll
        for (int kk = 0; kk < 16; kk++) {
            float4 a4 = *reinterpret_cast<const float4*>(&As[kk][ty * 4]);
            float4 b4 = *reinterpret_cast<const float4*>(&Bs[kk][tx * 4]);
            float aa[4] = {a4.x, a4.y, a4.z, a4.w};
            float bb[4] = {b4.x, b4.y, b4.z, b4.w};
#pragma unroll
            for (int i = 0; i < 4; i++)
#pragma unroll
                for (int j = 0; j < 4; j++) acc[i][j] = fmaf(aa[i], bb[j], acc[i][j]);
        }
        __syncthreads();
    }
#pragma unroll
    for (int i = 0; i < 4; i++) {
        int m = m0 + ty * 4 + i;
        float yv = 0.f;
        if (yvec) yv = (m == 0) ? 0.f : yvec[m - 1];
#pragma unroll
        for (int j = 0; j < 4; j++) {
            int n = n0 + tx * 4 + j;
            if (n < N) {
                float v = acc[i][j] + (bias ? bias[n] : 0.f);
                if (wy) v = fmaf(yv, wy[n], v);
                C[(size_t)m * N + n] = v;
            }
        }
    }
}

__global__ void __launch_bounds__(256) gemm1_kernel(const float* __restrict__ x,
                                                    const float* __restrict__ b_in) {
    gemm_nt_body(x, g_WinT, g_xs, TSTEPS, FDIM, DIN, b_in, nullptr, nullptr);
}
__global__ void __launch_bounds__(256) gemm2_kernel(const float* __restrict__ y) {
    gemm_nt_body(g_xs, g_Wx, g_gx, TSTEPS, G4, FDIM, g_bsum, y, g_wy);
}

// ---------------- fused kernel shared state ----------------
struct Shm {
    __align__(16) float h[4][HID];         // quad-buffered hidden (dsmem broadcast target)
    __align__(16) float Wk[HID * KDIM];    // consumer: W_k
    __align__(8)  float Ws[HID];
    __align__(8)  float bk[KDIM];
    __align__(8)  float key[KDIM];
    __align__(8)  float kn[KDIM];
    float wsum[4];
    float sig, bs;
    __align__(16) unsigned pflag[7];       // producer r published h up to step pflag[r]
    unsigned cflag;                        // consumer finished reading h_{cflag-1} (s counter)
};

__global__ void __cluster_dims__(CLSZ, 1, 1) __launch_bounds__(256, 1)
fused_kernel(const float* __restrict__ W_hh,
             const float* __restrict__ W_k, const float* __restrict__ b_k,
             const float* __restrict__ W_s, const float* __restrict__ b_s,
             float* __restrict__ out)
{
    __shared__ Shm S;
    const int tid = threadIdx.x;
    const uint32_t rank = my_cluster_rank();
    const bool is_consumer = (rank == CLSZ - 1);

    const uint32_t pflagA = smem_u32(&S.pflag[0]);
    const uint32_t cflagA = smem_u32(&S.cflag);
    if (tid < 7)  S.pflag[tid] = 0;
    if (tid == 7) S.cflag = 0;
    if (tid < HID) {
        S.h[0][tid] = 0.f; S.h[1][tid] = 0.f; S.h[2][tid] = 0.f; S.h[3][tid] = 0.f;
    }

    // remote flag handle: thread i (i<8) targets rank i's copy of MY flag slot
    uint32_t r_flag_mine = 0;
    if (tid < CLSZ) {
        uint32_t myslotA = is_consumer ? cflagA : (pflagA + 4u * rank);
        r_flag_mine = mapa_u32(myslotA, (uint32_t)tid);
    }

    // ---------- producer init: units 30,30,30,30,30,30,20 (even bases for u64 stores) ----------
    const int units = is_consumer ? 0 : ((rank < 6) ? 30 : 20);
    const int base  = 30 * (int)rank;            // rank 6 -> 180
    const int nact  = 8 * units;                 // 240 / 160
    const bool act  = tid < nact;
    const int u   = tid >> 3;                    // unit within CTA
    const int sub = tid & 7;                     // 2*gate + cc
    const int g   = sub >> 1;
    const int cc  = sub & 1;
    const int grow = act ? (g * HID + base + u) : 0;

    unsigned long long w[50];
    if (act) {
        const unsigned long long* wp =
            reinterpret_cast<const unsigned long long*>(W_hh + (size_t)grow * HID + cc * 100);
#pragma unroll
        for (int q = 0; q < 50; q++) w[q] = wp[q];
    }
    unsigned mask = 0;
    if (act) {
        int rem = nact - (tid & ~31);
        mask = (rem >= 32) ? 0xffffffffu : ((1u << rem) - 1u);
    }
    const unsigned submask = mask & 0x01010101u;  // sub==0 lanes of this warp
    uint32_t r_h[CLSZ];
    if (act && sub == 0) {
        uint32_t hA = smem_u32(&S.h[0][0]);
#pragma unroll
        for (int p = 0; p < CLSZ; p++) r_h[p] = mapa_u32(hA, (uint32_t)p);
    }

    // ---------- consumer init ----------
    unsigned long long M2[20];
    float wr = 0.f;
    if (is_consumer) {
        for (int i = tid; i < HID * KDIM; i += 256) S.Wk[i] = W_k[i];
        for (int i = tid; i < HID; i += 256) S.Ws[i] = W_s[i];
        if (tid < KDIM) S.bk[tid] = b_k[tid];
        if (tid == 0)   S.bs = b_s[0];
        if (tid < NSLOT) {
#pragma unroll
            for (int q = 0; q < 20; q++) M2[q] = pack2(1e-6f, 1e-6f);
            wr = (tid == 0) ? 1.f : 0.f;
        }
    }

    __syncthreads();
    cluster_sync_();   // flags + h zeroed everywhere before any traffic

    if (!is_consumer) {
        // ================= LSTM producer =================
        float cst = 0.f;
        float gxv = (act && cc == 0) ? g_gx[grow] : 0.f;

        for (int t = 0; t < TSTEPS; t++) {
            // prefetch next gx BEFORE the poll so its latency hides under the wait
            float gxn = 0.f;
            if (act && cc == 0) {
                int tn = (t + 1 < TSTEPS) ? (t + 1) : t;
                gxn = g_gx[(size_t)tn * G4 + grow];
            }
            // wait for h_t: every producer published step t (warp 0 polls, bar releases)
            if (t >= 1 && tid < 32) warp_poll_pflags(pflagA, (unsigned)t);
            __syncthreads();

            if (act) {
                const unsigned long long* h8 =
                    reinterpret_cast<const unsigned long long*>(&S.h[t & 3][cc * 100]);
                unsigned long long a0 = 0, a1 = 0, a2 = 0, a3 = 0;
#pragma unroll
                for (int q = 0; q < 48; q += 4) {
                    fma2(a0, w[q],     h8[q]);
                    fma2(a1, w[q + 1], h8[q + 1]);
                    fma2(a2, w[q + 2], h8[q + 2]);
                    fma2(a3, w[q + 3], h8[q + 3]);
                }
                fma2(a0, w[48], h8[48]);
                fma2(a1, w[49], h8[49]);
                float2 f0 = unpack2(a0), f1 = unpack2(a1), f2 = unpack2(a2), f3 = unpack2(a3);
                float dsum = ((f0.x + f0.y) + (f1.x + f1.y)) + ((f2.x + f2.y) + (f3.x + f3.y));
                dsum += __shfl_xor_sync(mask, dsum, 1);          // combine k-halves
                float av = 0.f;
                if (cc == 0) {
                    float gs = dsum + gxv;
                    av = (g == 2) ? ftanh(gs) : fsigmoid(gs);    // gate activation (even lanes)
                }
                float fv = __shfl_down_sync(mask, av, 2);
                float gv = __shfl_down_sync(mask, av, 4);
                float ov = __shfl_down_sync(mask, av, 6);
                if (sub == 0) {
                    cst = fv * cst + av * gv;
                    float h = ov * ftanh(cst);
                    float hhi = __shfl_down_sync(submask, h, 8); // partner unit u+1
                    if ((u & 1) == 0) {
                        // h_{t+1} -> buffer (t+1)&3, which held h_{t-3}:
                        // consumer must have finished reading it (cflag >= t-3)
                        if (t >= 4) { while (ld_acquire_u32(cflagA) < (unsigned)(t - 3)) {} }
                        const unsigned long long hv = pack2(h, hhi);
                        const uint32_t off = (uint32_t)(((t + 1) & 3) * HID + base + u) * 4u;
#pragma unroll
                        for (int p = 0; p < CLSZ; p++) dsmem_st_u64(r_h[p] + off, hv);
                    }
                }
            }
            gxv = gxn;
            __syncthreads();                     // all h stores issued before release
            if (tid < CLSZ) st_release_u32(r_flag_mine, (unsigned)(t + 1));
        }
        cluster_sync_();   // keep smem alive for in-flight remote ops
        return;
    }

    // ================= consumer: keys + sigma + MANN =================
    const int kk_ = tid >> 2, kp = tid & 3;      // keys mapping (tid<160)
    const int sp  = tid - 160;                   // sigma mapping (160<=tid<168)

    for (int s = 1; s <= TSTEPS; s++) {
        if (tid < 32) warp_poll_pflags(pflagA, (unsigned)s);   // h_s delivered
        __syncthreads();
        const float* hb = &S.h[s & 3][0];        // hiddens[s-1]

        // ---- keys (160 thr, 4/output) + sigma (8 thr) : the only readers of hb ----
        if (tid < 160) {
            const float* wp = &S.Wk[(kp * 50) * KDIM + kk_];
            const float* hp = &hb[kp * 50];
            float a = 0.f, b = 0.f;
#pragma unroll
            for (int i = 0; i < 50; i += 2) {
                a = fmaf(hp[i],     wp[i * KDIM],       a);
                b = fmaf(hp[i + 1], wp[(i + 1) * KDIM], b);
            }
            float acc = a + b;
            acc += __shfl_xor_sync(0xffffffffu, acc, 1);
            acc += __shfl_xor_sync(0xffffffffu, acc, 2);
            if (kp == 0) {
                float kv = ftanh(acc + S.bk[kk_]);
                S.key[kk_] = kv;
                S.kn[kk_]  = kv / fmaxf(fabsf(kv), EPSF);
            }
        } else if (tid < 168) {
            float a = 0.f;
#pragma unroll
            for (int i = 0; i < 25; i++) a = fmaf(hb[sp * 25 + i], S.Ws[sp * 25 + i], a);
            a += __shfl_xor_sync(0xFFu, a, 4);
            a += __shfl_xor_sync(0xFFu, a, 2);
            a += __shfl_xor_sync(0xFFu, a, 1);
            if (sp == 0) S.sig = fsigmoid(a + S.bs);
        }
        __syncthreads();                         // all reads of hb complete
        if (tid < CLSZ) st_release_u32(r_flag_mine, (unsigned)s);   // done with h_s

        // ---- MANN step (128 threads, one slot each) ----
        float e = 0.f;
        if (tid < NSLOT) {
            const float sg = S.sig;
            const float ww = fmaf(sg, wr, 1.f - sg);     // wlu mask == 1 identically
            const unsigned long long ww2 = pack2(ww, ww);
            const unsigned long long* k2  = reinterpret_cast<const unsigned long long*>(S.key);
            const unsigned long long* kn2 = reinterpret_cast<const unsigned long long*>(S.kn);
            unsigned long long n0 = 0, n1 = 0, d0 = 0, d1 = 0;
#pragma unroll
            for (int q = 0; q < 20; q += 2) {
                fma2(M2[q],     ww2, k2[q]);
                fma2(M2[q + 1], ww2, k2[q + 1]);
                fma2(n0, M2[q],     M2[q]);
                fma2(n1, M2[q + 1], M2[q + 1]);
                fma2(d0, M2[q],     kn2[q]);
                fma2(d1, M2[q + 1], kn2[q + 1]);
            }
            float2 na = unpack2(n0), nb = unpack2(n1), da = unpack2(d0), db = unpack2(d1);
            float ns  = (na.x + na.y) + (nb.x + nb.y);   // >= 4e-11, never 0
            float dot = (da.x + da.y) + (db.x + db.y);
            e = __expf(dot * rsqrtf(ns));                // |logit| <= sqrt(40)
            float acc = e;
#pragma unroll
            for (int off = 16; off > 0; off >>= 1) acc += __shfl_xor_sync(0xffffffffu, acc, off);
            if ((tid & 31) == 0) S.wsum[tid >> 5] = acc;
        }
        __syncthreads();
        if (tid < NSLOT) {
            float tot = (S.wsum[0] + S.wsum[1]) + (S.wsum[2] + S.wsum[3]);
            wr = __fdividef(e, tot);
        }
    }

    if (tid < NSLOT) {
#pragma unroll
        for (int q = 0; q < 20; q++) {
            float2 v = unpack2(M2[q]);
            out[tid * KDIM + 2 * q]     = v.x;
            out[tid * KDIM + 2 * q + 1] = v.y;
        }
    }
    cluster_sync_();   // keep smem alive for in-flight remote ops
}

// ---------------- launch ----------------
extern "C" void kernel_launch(void* const* d_in, const int* in_sizes, int n_in,
                              void* d_out, int out_size) {
    const float* x    = (const float*)d_in[0];
    const float* y    = (const float*)d_in[1];
    const float* W_in = (const float*)d_in[2];
    const float* b_in = (const float*)d_in[3];
    const float* W_ih = (const float*)d_in[4];
    const float* W_hh = (const float*)d_in[5];
    const float* b_ih = (const float*)d_in[6];
    const float* b_hh = (const float*)d_in[7];
    const float* W_k  = (const float*)d_in[8];
    const float* b_k  = (const float*)d_in[9];
    const float* W_s  = (const float*)d_in[10];
    const float* b_s  = (const float*)d_in[11];
    // gamma (d_in[12]) provably unused: wlu mask is identically 1, wu/gamma cancel

    prep_kernel<<<(G4 * FDIM + 255) / 256, 256>>>(W_in, W_ih, b_ih, b_hh);
    gemm1_kernel<<<dim3(FDIM / 64, TSTEPS / 64), 256>>>(x, b_in);
    gemm2_kernel<<<dim3((G4 + 63) / 64, TSTEPS / 64), 256>>>(y);
    fused_kernel<<<CLSZ, 256>>>(W_hh, W_k, b_k, W_s, b_s, (float*)d_out);
}

// round 10
// speedup vs baseline: 1.3189x; 1.1621x over previous
#include <cuda_runtime.h>
#include <cstdint>
#include <math.h>

#define TSTEPS 4096
#define DIN    512
#define FDIM   256
#define HID    200
#define G4     800
#define KDIM   40
#define NSLOT  128
#define EPSF   1e-12f
#define CLSZ   8

// ---------------- scratch (device globals) ----------------
__device__ float g_xs[TSTEPS * FDIM];
__device__ float g_gx[TSTEPS * G4];
__device__ float g_WinT[FDIM * DIN];
__device__ float g_Wx[G4 * FDIM];
__device__ float g_wy[G4];
__device__ float g_bsum[G4];
__device__ float g_WkT[KDIM * HID];   // W_k transposed: [40][200]

// ---------------- helpers ----------------
__device__ __forceinline__ float fsigmoid(float x) {
    return __fdividef(1.f, 1.f + __expf(-x));
}
__device__ __forceinline__ float ftanh(float x) {
    float a = fabsf(x);
    float e = __expf(-2.f * a);
    float r = __fdividef(1.f - e, 1.f + e);
    return copysignf(r, x);
}
__device__ __forceinline__ uint32_t smem_u32(const void* p) {
    return (uint32_t)__cvta_generic_to_shared(p);
}
__device__ __forceinline__ uint32_t my_cluster_rank() {
    uint32_t r; asm("mov.u32 %0, %%cluster_ctarank;" : "=r"(r)); return r;
}
__device__ __forceinline__ uint32_t mapa_u32(uint32_t laddr, uint32_t rank) {
    uint32_t r;
    asm("mapa.shared::cluster.u32 %0, %1, %2;" : "=r"(r) : "r"(laddr), "r"(rank));
    return r;
}
__device__ __forceinline__ void cluster_sync_() {
    asm volatile("barrier.cluster.arrive.aligned;" ::: "memory");
    asm volatile("barrier.cluster.wait.aligned;" ::: "memory");
}
__device__ __forceinline__ void dsmem_st_f32(uint32_t raddr, float v) {
    asm volatile("st.shared::cluster.f32 [%0], %1;" :: "r"(raddr), "f"(v) : "memory");
}
__device__ __forceinline__ void bar_sync_(int id, int cnt) {
    asm volatile("bar.sync %0, %1;" :: "r"(id), "r"(cnt) : "memory");
}
// packed fp32x2 FMA: d = a*b + d  (sm_100 FFMA2; ptxas never auto-fuses this)
__device__ __forceinline__ void fma2(unsigned long long& d, unsigned long long a, unsigned long long b) {
    asm("fma.rn.f32x2 %0, %1, %2, %0;" : "+l"(d) : "l"(a), "l"(b));
}
__device__ __forceinline__ float2 unpack2(unsigned long long v) {
    float2 r; asm("mov.b64 {%0, %1}, %2;" : "=f"(r.x), "=f"(r.y) : "l"(v)); return r;
}
__device__ __forceinline__ unsigned long long pack2(float x, float y) {
    unsigned long long v; asm("mov.b64 %0, {%1, %2};" : "=l"(v) : "f"(x), "f"(y)); return v;
}

// ---------------- prep ----------------
__global__ void prep_kernel(const float* __restrict__ W_in, const float* __restrict__ W_ih,
                            const float* __restrict__ b_ih, const float* __restrict__ b_hh,
                            const float* __restrict__ W_k) {
    int idx = blockIdx.x * blockDim.x + threadIdx.x;
    if (idx < G4 * FDIM) {
        int n = idx / FDIM, k = idx % FDIM;
        g_Wx[idx] = W_ih[n * (FDIM + 1) + k];
    }
    if (idx < DIN * FDIM) {
        int k = idx / FDIM, n = idx % FDIM;
        g_WinT[n * DIN + k] = W_in[idx];
    }
    if (idx < G4) {
        g_wy[idx]   = W_ih[idx * (FDIM + 1) + FDIM];
        g_bsum[idx] = b_ih[idx] + b_hh[idx];
    }
    if (idx < KDIM * HID) {
        int k = idx / HID, h = idx % HID;
        g_WkT[idx] = W_k[h * KDIM + k];
    }
}

// ---------------- GEMM C = A * B^T ----------------
__device__ __forceinline__ void gemm_nt_body(
    const float* __restrict__ A, const float* __restrict__ B, float* __restrict__ C,
    int M, int N, int K,
    const float* __restrict__ bias, const float* __restrict__ yvec, const float* __restrict__ wy)
{
    __shared__ __align__(16) float As[16][64];
    __shared__ __align__(16) float Bs[16][64];
    const int m0 = blockIdx.y * 64, n0 = blockIdx.x * 64;
    const int tid = threadIdx.x;
    const int tx = tid % 16, ty = tid / 16;
    const int lr = tid / 4, lc4 = (tid % 4) * 4;

    float acc[4][4];
#pragma unroll
    for (int i = 0; i < 4; i++)
#pragma unroll
        for (int j = 0; j < 4; j++) acc[i][j] = 0.f;

    for (int k0 = 0; k0 < K; k0 += 16) {
        float4 av = *reinterpret_cast<const float4*>(A + (size_t)(m0 + lr) * K + k0 + lc4);
        As[lc4 + 0][lr] = av.x; As[lc4 + 1][lr] = av.y;
        As[lc4 + 2][lr] = av.z; As[lc4 + 3][lr] = av.w;
        float4 bv = make_float4(0.f, 0.f, 0.f, 0.f);
        if (n0 + lr < N) bv = *reinterpret_cast<const float4*>(B + (size_t)(n0 + lr) * K + k0 + lc4);
        Bs[lc4 + 0][lr] = bv.x; Bs[lc4 + 1][lr] = bv.y;
        Bs[lc4 + 2][lr] = bv.z; Bs[lc4 + 3][lr] = bv.w;
        __syncthreads();
#pragma unroll
        for (int kk = 0; kk < 16; kk++) {
            float4 a4 = *reinterpret_cast<const float4*>(&As[kk][ty * 4]);
            float4 b4 = *reinterpret_cast<const float4*>(&Bs[kk][tx * 4]);
            float aa[4] = {a4.x, a4.y, a4.z, a4.w};
            float bb[4] = {b4.x, b4.y, b4.z, b4.w};
#pragma unroll
            for (int i = 0; i < 4; i++)
#pragma unroll
                for (int j = 0; j < 4; j++) acc[i][j] = fmaf(aa[i], bb[j], acc[i][j]);
        }
        __syncthreads();
    }
#pragma unroll
    for (int i = 0; i < 4; i++) {
        int m = m0 + ty * 4 + i;
        float yv = 0.f;
        if (yvec) yv = (m == 0) ? 0.f : yvec[m - 1];
#pragma unroll
        for (int j = 0; j < 4; j++) {
            int n = n0 + tx * 4 + j;
            if (n < N) {
                float v = acc[i][j] + (bias ? bias[n] : 0.f);
                if (wy) v = fmaf(yv, wy[n], v);
                C[(size_t)m * N + n] = v;
            }
        }
    }
}

__global__ void __launch_bounds__(256) gemm1_kernel(const float* __restrict__ x,
                                                    const float* __restrict__ b_in) {
    gemm_nt_body(x, g_WinT, g_xs, TSTEPS, FDIM, DIN, b_in, nullptr, nullptr);
}
__global__ void __launch_bounds__(256) gemm2_kernel(const float* __restrict__ y) {
    gemm_nt_body(g_xs, g_Wx, g_gx, TSTEPS, G4, FDIM, g_bsum, y, g_wy);
}

// ---------------- fused kernel shared state ----------------
struct Shm {
    __align__(16) float h[2][HID];          // double-buffered hidden (dsmem broadcast target)
    __align__(16) float WkT[KDIM * HID];    // consumer: W_k transposed [40][200]
    __align__(8)  float Ws[HID];
    __align__(8)  float bk[KDIM];
    __align__(16) float key[2][KDIM];       // double-buffered (keys pipeline vs MANN)
    __align__(16) float kn[2][KDIM];
    float sig[2];
    float wsum[4];
    float bs;
};

// MANN step on buffer kb (threads 0..127 only; uses named barrier 1)
__device__ __forceinline__ void mann_step(Shm& S, int tid, int kb,
                                          unsigned long long* M2, float& wr)
{
    const float sg = S.sig[kb];
    const float ww = fmaf(sg, wr, 1.f - sg);        // wlu mask == 1 identically
    const unsigned long long ww2 = pack2(ww, ww);
    const unsigned long long* k2  = reinterpret_cast<const unsigned long long*>(S.key[kb]);
    const unsigned long long* kn2 = reinterpret_cast<const unsigned long long*>(S.kn[kb]);
    unsigned long long n0 = 0, n1 = 0, d0 = 0, d1 = 0;
#pragma unroll
    for (int q = 0; q < 20; q += 2) {
        fma2(M2[q],     ww2, k2[q]);
        fma2(M2[q + 1], ww2, k2[q + 1]);
        fma2(n0, M2[q],     M2[q]);
        fma2(n1, M2[q + 1], M2[q + 1]);
        fma2(d0, M2[q],     kn2[q]);
        fma2(d1, M2[q + 1], kn2[q + 1]);
    }
    float2 na = unpack2(n0), nb = unpack2(n1), da = unpack2(d0), db = unpack2(d1);
    float ns  = (na.x + na.y) + (nb.x + nb.y);      // >= 4e-11, never 0
    float dot = (da.x + da.y) + (db.x + db.y);
    float e = __expf(dot * rsqrtf(ns));             // |logit| <= sqrt(40)
    float acc = e;
#pragma unroll
    for (int off = 16; off > 0; off >>= 1) acc += __shfl_xor_sync(0xffffffffu, acc, off);
    if ((tid & 31) == 0) S.wsum[tid >> 5] = acc;
    bar_sync_(1, 128);                              // MANN group only
    float tot = (S.wsum[0] + S.wsum[1]) + (S.wsum[2] + S.wsum[3]);
    wr = __fdividef(e, tot);
}

// keys + sigma from hidden vector hb into buffer kb (threads 128..215)
__device__ __forceinline__ void keys_sigma(Shm& S, int tid, const float* __restrict__ hb, int kb)
{
    if (tid < 208) {                 // keys: 2 threads per output (tid 128..207)
        const int k = (tid - 128) >> 1, half = (tid - 128) & 1;
        const unsigned mask = (tid < 192) ? 0xffffffffu : 0x0000FFFFu;
        const unsigned long long* wp =
            reinterpret_cast<const unsigned long long*>(&S.WkT[k * HID + half * 100]);
        const unsigned long long* hp =
            reinterpret_cast<const unsigned long long*>(hb + half * 100);
        // 100 floats = 50 u64 per thread (R9 bug: only covered 25 u64)
        unsigned long long a0 = 0, a1 = 0, a2 = 0, a3 = 0;
#pragma unroll
        for (int i = 0; i < 48; i += 4) {
            fma2(a0, wp[i],     hp[i]);
            fma2(a1, wp[i + 1], hp[i + 1]);
            fma2(a2, wp[i + 2], hp[i + 2]);
            fma2(a3, wp[i + 3], hp[i + 3]);
        }
        fma2(a0, wp[48], hp[48]);
        fma2(a1, wp[49], hp[49]);
        float2 xa = unpack2(a0), xb = unpack2(a1), xc = unpack2(a2), xd = unpack2(a3);
        float acc = ((xa.x + xa.y) + (xb.x + xb.y)) + ((xc.x + xc.y) + (xd.x + xd.y));
        acc += __shfl_xor_sync(mask, acc, 1);
        if (half == 0) {
            float kv = ftanh(acc + S.bk[k]);
            S.key[kb][k] = kv;
            S.kn[kb][k]  = kv / fmaxf(fabsf(kv), EPSF);
        }
    } else if (tid < 216) {          // sigma: 8 threads (warp 6 lanes 16..23)
        const int p = tid - 208;
        float a = 0.f;
#pragma unroll
        for (int i = 0; i < 25; i++) a = fmaf(hb[p * 25 + i], S.Ws[p * 25 + i], a);
        a += __shfl_xor_sync(0x00FF0000u, a, 4);
        a += __shfl_xor_sync(0x00FF0000u, a, 2);
        a += __shfl_xor_sync(0x00FF0000u, a, 1);
        if (p == 0) S.sig[kb] = fsigmoid(a + S.bs);
    }
}

__global__ void __cluster_dims__(CLSZ, 1, 1) __launch_bounds__(256, 1)
fused_kernel(const float* __restrict__ W_hh,
             const float* __restrict__ b_k,
             const float* __restrict__ W_s, const float* __restrict__ b_s,
             float* __restrict__ out)
{
    __shared__ Shm S;
    const int tid = threadIdx.x;
    const uint32_t rank = my_cluster_rank();
    const bool is_consumer = (rank == CLSZ - 1);

    if (tid < HID) { S.h[0][tid] = 0.f; S.h[1][tid] = 0.f; }

    // ---------- producer init (R4-identical: units 29x6 + 26) ----------
    const int units = is_consumer ? 0 : ((rank < 6) ? 29 : 26);
    const int base  = 29 * (int)rank;            // rank 6 -> 174
    const int nact  = 8 * units;
    const bool act  = tid < nact;
    const int u   = tid >> 3;                    // unit within CTA
    const int sub = tid & 7;                     // 2*gate + cc
    const int g   = sub >> 1;
    const int cc  = sub & 1;
    const int grow = act ? (g * HID + base + u) : 0;

    unsigned long long w[50];
    if (act) {
        const unsigned long long* wp =
            reinterpret_cast<const unsigned long long*>(W_hh + (size_t)grow * HID + cc * 100);
#pragma unroll
        for (int q = 0; q < 50; q++) w[q] = wp[q];
    }
    unsigned mask = 0;
    if (act) {
        int rem = nact - (tid & ~31);
        mask = (rem >= 32) ? 0xffffffffu : ((1u << rem) - 1u);
    }
    uint32_t r_h[CLSZ];
    if (act && sub == 0) {
        uint32_t hA = smem_u32(&S.h[0][0]);
#pragma unroll
        for (int p = 0; p < CLSZ; p++) r_h[p] = mapa_u32(hA, (uint32_t)p);
    }

    // ---------- consumer init ----------
    unsigned long long M2[20];
    float wr = 0.f;
    if (is_consumer) {
        for (int i = tid; i < KDIM * HID; i += 256) S.WkT[i] = g_WkT[i];
        for (int i = tid; i < HID; i += 256) S.Ws[i] = W_s[i];
        if (tid < KDIM) S.bk[tid] = b_k[tid];
        if (tid == 0)   S.bs = b_s[0];
        if (tid < NSLOT) {
#pragma unroll
            for (int q = 0; q < 20; q++) M2[q] = pack2(1e-6f, 1e-6f);
            wr = (tid == 0) ? 1.f : 0.f;
        }
    }

    __syncthreads();
    cluster_sync_();   // h zeroed everywhere before any traffic

    float cst = 0.f;
    float gxv = (act && cc == 0) ? g_gx[grow] : 0.f;

    for (int t = 0; t < TSTEPS; t++) {
        if (!is_consumer) {
            // ================= LSTM producer (R4-identical) =================
            const int buf = t & 1, bw = buf ^ 1;
            float gxn = 0.f;
            if (act && cc == 0) {
                int tn = (t + 1 < TSTEPS) ? (t + 1) : t;   // prefetch next gx
                gxn = g_gx[(size_t)tn * G4 + grow];
            }
            if (act) {
                const unsigned long long* h8 =
                    reinterpret_cast<const unsigned long long*>(&S.h[buf][cc * 100]);
                unsigned long long a0 = 0, a1 = 0, a2 = 0, a3 = 0;
#pragma unroll
                for (int q = 0; q < 48; q += 4) {
                    fma2(a0, w[q],     h8[q]);
                    fma2(a1, w[q + 1], h8[q + 1]);
                    fma2(a2, w[q + 2], h8[q + 2]);
                    fma2(a3, w[q + 3], h8[q + 3]);
                }
                fma2(a0, w[48], h8[48]);
                fma2(a1, w[49], h8[49]);
                float2 f0 = unpack2(a0), f1 = unpack2(a1), f2 = unpack2(a2), f3 = unpack2(a3);
                float dsum = ((f0.x + f0.y) + (f1.x + f1.y)) + ((f2.x + f2.y) + (f3.x + f3.y));
                dsum += __shfl_xor_sync(mask, dsum, 1);          // combine k-halves
                float av = 0.f;
                if (cc == 0) {
                    float gs = dsum + gxv;
                    av = (g == 2) ? ftanh(gs) : fsigmoid(gs);    // gate activation (even lanes)
                }
                float fv = __shfl_down_sync(mask, av, 2);
                float gv = __shfl_down_sync(mask, av, 4);
                float ov = __shfl_down_sync(mask, av, 6);
                if (sub == 0) {
                    cst = fv * cst + av * gv;
                    float h = ov * ftanh(cst);
                    const uint32_t off = (uint32_t)(bw * HID + base + u) * 4u;
#pragma unroll
                    for (int p = 0; p < CLSZ; p++) dsmem_st_f32(r_h[p] + off, h);
                }
            }
            gxv = gxn;
        } else {
            // ============ consumer: keys(t-1) on warps 4-7 || MANN(t-2) on warps 0-3 ============
            if (tid >= 128) {
                if (t >= 1) keys_sigma(S, tid, &S.h[t & 1][0], t & 1);
            } else if (t >= 2) {
                mann_step(S, tid, (t - 1) & 1, M2, wr);
            }
            __syncthreads();   // MANN done with key[(t-1)&1] before keys overwrite next iter
        }
        cluster_sync_();       // release h_{t+1} writes; acquire for next step's reads
    }

    if (is_consumer) {
        // tail 1: keys for hiddens[4095] (in h[0]) || MANN for hiddens[4094] (key[1])
        if (tid >= 128) keys_sigma(S, tid, &S.h[0][0], 0);
        else            mann_step(S, tid, 1, M2, wr);
        __syncthreads();
        // tail 2: MANN for hiddens[4095] (key[0])
        if (tid < 128)  mann_step(S, tid, 0, M2, wr);

        if (tid < NSLOT) {
#pragma unroll
            for (int q = 0; q < 20; q++) {
                float2 v = unpack2(M2[q]);
                out[tid * KDIM + 2 * q]     = v.x;
                out[tid * KDIM + 2 * q + 1] = v.y;
            }
        }
    }
}

// ---------------- launch ----------------
extern "C" void kernel_launch(void* const* d_in, const int* in_sizes, int n_in,
                              void* d_out, int out_size) {
    const float* x    = (const float*)d_in[0];
    const float* y    = (const float*)d_in[1];
    const float* W_in = (const float*)d_in[2];
    const float* b_in = (const float*)d_in[3];
    const float* W_ih = (const float*)d_in[4];
    const float* W_hh = (const float*)d_in[5];
    const float* b_ih = (const float*)d_in[6];
    const float* b_hh = (const float*)d_in[7];
    const float* W_k  = (const float*)d_in[8];
    const float* b_k  = (const float*)d_in[9];
    const float* W_s  = (const float*)d_in[10];
    const float* b_s  = (const float*)d_in[11];
    // gamma (d_in[12]) provably unused: wlu mask is identically 1, wu/gamma cancel

    prep_kernel<<<(G4 * FDIM + 255) / 256, 256>>>(W_in, W_ih, b_ih, b_hh, W_k);
    gemm1_kernel<<<dim3(FDIM / 64, TSTEPS / 64), 256>>>(x, b_in);
    gemm2_kernel<<<dim3((G4 + 63) / 64, TSTEPS / 64), 256>>>(y);
    fused_kernel<<<CLSZ, 256>>>(W_hh, b_k, W_s, b_s, (float*)d_out);
}

// round 11
// speedup vs baseline: 1.3442x; 1.0192x over previous
#include <cuda_runtime.h>
#include <cstdint>
#include <math.h>

#define TSTEPS 4096
#define DIN    512
#define FDIM   256
#define HID    200
#define G4     800
#define KDIM   40
#define NSLOT  128
#define EPSF   1e-12f
#define CLSZ   8

// ---------------- scratch (device globals) ----------------
__device__ float g_xs[TSTEPS * FDIM];
__device__ float g_gx[TSTEPS * G4];
__device__ float g_WinT[FDIM * DIN];
__device__ float g_Wx[G4 * FDIM];
__device__ float g_wy[G4];
__device__ float g_bsum[G4];
__device__ float g_WkT[KDIM * HID];   // W_k transposed: [40][200]

// ---------------- helpers ----------------
__device__ __forceinline__ float fsigmoid(float x) {
    return __fdividef(1.f, 1.f + __expf(-x));
}
__device__ __forceinline__ float ftanh(float x) {
    float a = fabsf(x);
    float e = __expf(-2.f * a);
    float r = __fdividef(1.f - e, 1.f + e);
    return copysignf(r, x);
}
__device__ __forceinline__ uint32_t smem_u32(const void* p) {
    return (uint32_t)__cvta_generic_to_shared(p);
}
__device__ __forceinline__ uint32_t my_cluster_rank() {
    uint32_t r; asm("mov.u32 %0, %%cluster_ctarank;" : "=r"(r)); return r;
}
__device__ __forceinline__ uint32_t mapa_u32(uint32_t laddr, uint32_t rank) {
    uint32_t r;
    asm("mapa.shared::cluster.u32 %0, %1, %2;" : "=r"(r) : "r"(laddr), "r"(rank));
    return r;
}
__device__ __forceinline__ void cluster_sync_() {
    asm volatile("barrier.cluster.arrive.aligned;" ::: "memory");
    asm volatile("barrier.cluster.wait.aligned;" ::: "memory");
}
__device__ __forceinline__ void dsmem_st_f32(uint32_t raddr, float v) {
    asm volatile("st.shared::cluster.f32 [%0], %1;" :: "r"(raddr), "f"(v) : "memory");
}
__device__ __forceinline__ void bar_sync_(int id, int cnt) {
    asm volatile("bar.sync %0, %1;" :: "r"(id), "r"(cnt) : "memory");
}
// 16B vector load from shared (LDS.128) into two u64
__device__ __forceinline__ void lds128(unsigned long long& x, unsigned long long& y, uint32_t addr) {
    asm volatile("ld.shared.v2.u64 {%0, %1}, [%2];" : "=l"(x), "=l"(y) : "r"(addr));
}
// packed fp32x2 FMA: d = a*b + d  (sm_100 FFMA2; ptxas never auto-fuses this)
__device__ __forceinline__ void fma2(unsigned long long& d, unsigned long long a, unsigned long long b) {
    asm("fma.rn.f32x2 %0, %1, %2, %0;" : "+l"(d) : "l"(a), "l"(b));
}
__device__ __forceinline__ float2 unpack2(unsigned long long v) {
    float2 r; asm("mov.b64 {%0, %1}, %2;" : "=f"(r.x), "=f"(r.y) : "l"(v)); return r;
}
__device__ __forceinline__ unsigned long long pack2(float x, float y) {
    unsigned long long v; asm("mov.b64 %0, {%1, %2};" : "=l"(v) : "f"(x), "f"(y)); return v;
}

// ---------------- prep ----------------
__global__ void prep_kernel(const float* __restrict__ W_in, const float* __restrict__ W_ih,
                            const float* __restrict__ b_ih, const float* __restrict__ b_hh,
                            const float* __restrict__ W_k) {
    int idx = blockIdx.x * blockDim.x + threadIdx.x;
    if (idx < G4 * FDIM) {
        int n = idx / FDIM, k = idx % FDIM;
        g_Wx[idx] = W_ih[n * (FDIM + 1) + k];
    }
    if (idx < DIN * FDIM) {
        int k = idx / FDIM, n = idx % FDIM;
        g_WinT[n * DIN + k] = W_in[idx];
    }
    if (idx < G4) {
        g_wy[idx]   = W_ih[idx * (FDIM + 1) + FDIM];
        g_bsum[idx] = b_ih[idx] + b_hh[idx];
    }
    if (idx < KDIM * HID) {
        int k = idx / HID, h = idx % HID;
        g_WkT[idx] = W_k[h * KDIM + k];
    }
}

// ---------------- GEMM C = A * B^T ----------------
__device__ __forceinline__ void gemm_nt_body(
    const float* __restrict__ A, const float* __restrict__ B, float* __restrict__ C,
    int M, int N, int K,
    const float* __restrict__ bias, const float* __restrict__ yvec, const float* __restrict__ wy)
{
    __shared__ __align__(16) float As[16][64];
    __shared__ __align__(16) float Bs[16][64];
    const int m0 = blockIdx.y * 64, n0 = blockIdx.x * 64;
    const int tid = threadIdx.x;
    const int tx = tid % 16, ty = tid / 16;
    const int lr = tid / 4, lc4 = (tid % 4) * 4;

    float acc[4][4];
#pragma unroll
    for (int i = 0; i < 4; i++)
#pragma unroll
        for (int j = 0; j < 4; j++) acc[i][j] = 0.f;

    for (int k0 = 0; k0 < K; k0 += 16) {
        float4 av = *reinterpret_cast<const float4*>(A + (size_t)(m0 + lr) * K + k0 + lc4);
        As[lc4 + 0][lr] = av.x; As[lc4 + 1][lr] = av.y;
        As[lc4 + 2][lr] = av.z; As[lc4 + 3][lr] = av.w;
        float4 bv = make_float4(0.f, 0.f, 0.f, 0.f);
        if (n0 + lr < N) bv = *reinterpret_cast<const float4*>(B + (size_t)(n0 + lr) * K + k0 + lc4);
        Bs[lc4 + 0][lr] = bv.x; Bs[lc4 + 1][lr] = bv.y;
        Bs[lc4 + 2][lr] = bv.z; Bs[lc4 + 3][lr] = bv.w;
        __syncthreads();
#pragma unroll
        for (int kk = 0; kk < 16; kk++) {
            float4 a4 = *reinterpret_cast<const float4*>(&As[kk][ty * 4]);
            float4 b4 = *reinterpret_cast<const float4*>(&Bs[kk][tx * 4]);
            float aa[4] = {a4.x, a4.y, a4.z, a4.w};
            float bb[4] = {b4.x, b4.y, b4.z, b4.w};
#pragma unroll
            for (int i = 0; i < 4; i++)
#pragma unroll
                for (int j = 0; j < 4; j++) acc[i][j] = fmaf(aa[i], bb[j], acc[i][j]);
        }
        __syncthreads();
    }
#pragma unroll
    for (int i = 0; i < 4; i++) {
        int m = m0 + ty * 4 + i;
        float yv = 0.f;
        if (yvec) yv = (m == 0) ? 0.f : yvec[m - 1];
#pragma unroll
        for (int j = 0; j < 4; j++) {
            int n = n0 + tx * 4 + j;
            if (n < N) {
                float v = acc[i][j] + (bias ? bias[n] : 0.f);
                if (wy) v = fmaf(yv, wy[n], v);
                C[(size_t)m * N + n] = v;
            }
        }
    }
}

__global__ void __launch_bounds__(256) gemm1_kernel(const float* __restrict__ x,
                                                    const float* __restrict__ b_in) {
    gemm_nt_body(x, g_WinT, g_xs, TSTEPS, FDIM, DIN, b_in, nullptr, nullptr);
}
__global__ void __launch_bounds__(256) gemm2_kernel(const float* __restrict__ y) {
    gemm_nt_body(g_xs, g_Wx, g_gx, TSTEPS, G4, FDIM, g_bsum, y, g_wy);
}

// ---------------- fused kernel shared state ----------------
struct Shm {
    __align__(16) float h[2][HID];          // double-buffered hidden (dsmem broadcast target)
    __align__(8)  float Ws[HID];
    __align__(8)  float bk[KDIM];
    __align__(16) float key[2][KDIM];       // double-buffered (keys pipeline vs MANN)
    __align__(16) float kn[2][KDIM];
    float sig[2];
    float wsum[4];
    float bs;
};

// MANN step on buffer kb (threads 0..127 only; uses named barrier 1)
__device__ __forceinline__ void mann_step(Shm& S, int tid, int kb,
                                          unsigned long long* M2, float& wr)
{
    const float sg = S.sig[kb];
    const float ww = fmaf(sg, wr, 1.f - sg);        // wlu mask == 1 identically
    const unsigned long long ww2 = pack2(ww, ww);
    const uint32_t kaddr  = smem_u32(&S.key[kb][0]);
    const uint32_t knaddr = smem_u32(&S.kn[kb][0]);
    unsigned long long n0 = 0, n1 = 0, d0 = 0, d1 = 0;
#pragma unroll
    for (int q = 0; q < 20; q += 2) {
        unsigned long long k0, k1, kn0, kn1;
        lds128(k0,  k1,  kaddr  + (uint32_t)q * 8u);
        lds128(kn0, kn1, knaddr + (uint32_t)q * 8u);
        fma2(M2[q],     ww2, k0);
        fma2(M2[q + 1], ww2, k1);
        fma2(n0, M2[q],     M2[q]);
        fma2(n1, M2[q + 1], M2[q + 1]);
        fma2(d0, M2[q],     kn0);
        fma2(d1, M2[q + 1], kn1);
    }
    float2 na = unpack2(n0), nb = unpack2(n1), da = unpack2(d0), db = unpack2(d1);
    float ns  = (na.x + na.y) + (nb.x + nb.y);      // >= 4e-11, never 0
    float dot = (da.x + da.y) + (db.x + db.y);
    float e = __expf(dot * rsqrtf(ns));             // |logit| <= sqrt(40)
    float acc = e;
#pragma unroll
    for (int off = 16; off > 0; off >>= 1) acc += __shfl_xor_sync(0xffffffffu, acc, off);
    if ((tid & 31) == 0) S.wsum[tid >> 5] = acc;
    bar_sync_(1, 128);                              // MANN group only
    float tot = (S.wsum[0] + S.wsum[1]) + (S.wsum[2] + S.wsum[3]);
    wr = __fdividef(e, tot);
}

// keys + sigma from hidden vector hb into buffer kb (threads 128..215)
// keys threads carry their WkT slice in registers (wk, 50 u64)
__device__ __forceinline__ void keys_sigma(Shm& S, int tid, const float* __restrict__ hb, int kb,
                                           const unsigned long long* wk)
{
    if (tid < 208) {                 // keys: 2 threads per output (tid 128..207)
        const int k = (tid - 128) >> 1, half = (tid - 128) & 1;
        const unsigned mask = (tid < 192) ? 0xffffffffu : 0x0000FFFFu;
        const uint32_t haddr = smem_u32(hb) + (uint32_t)half * 400u;
        unsigned long long a0 = 0, a1 = 0, a2 = 0, a3 = 0;
#pragma unroll
        for (int q = 0; q < 25; q++) {
            unsigned long long x, y;
            lds128(x, y, haddr + (uint32_t)q * 16u);
            if (q & 1) { fma2(a2, wk[2 * q], x); fma2(a3, wk[2 * q + 1], y); }
            else       { fma2(a0, wk[2 * q], x); fma2(a1, wk[2 * q + 1], y); }
        }
        float2 xa = unpack2(a0), xb = unpack2(a1), xc = unpack2(a2), xd = unpack2(a3);
        float acc = ((xa.x + xa.y) + (xb.x + xb.y)) + ((xc.x + xc.y) + (xd.x + xd.y));
        acc += __shfl_xor_sync(mask, acc, 1);
        if (half == 0) {
            float kv = ftanh(acc + S.bk[k]);
            S.key[kb][k] = kv;
            S.kn[kb][k]  = kv / fmaxf(fabsf(kv), EPSF);
        }
    } else if (tid < 216) {          // sigma: 8 threads (warp 6 lanes 16..23)
        const int p = tid - 208;
        float a = 0.f;
#pragma unroll
        for (int i = 0; i < 25; i++) a = fmaf(hb[p * 25 + i], S.Ws[p * 25 + i], a);
        a += __shfl_xor_sync(0x00FF0000u, a, 4);
        a += __shfl_xor_sync(0x00FF0000u, a, 2);
        a += __shfl_xor_sync(0x00FF0000u, a, 1);
        if (p == 0) S.sig[kb] = fsigmoid(a + S.bs);
    }
}

__global__ void __cluster_dims__(CLSZ, 1, 1) __launch_bounds__(256, 1)
fused_kernel(const float* __restrict__ W_hh,
             const float* __restrict__ b_k,
             const float* __restrict__ W_s, const float* __restrict__ b_s,
             float* __restrict__ out)
{
    __shared__ Shm S;
    const int tid = threadIdx.x;
    const uint32_t rank = my_cluster_rank();
    const bool is_consumer = (rank == CLSZ - 1);

    if (tid < HID) { S.h[0][tid] = 0.f; S.h[1][tid] = 0.f; }

    if (!is_consumer) {
        // ================= LSTM producer (R4/R10-identical math) =================
        const int units = (rank < 6) ? 29 : 26;
        const int base  = 29 * (int)rank;            // rank 6 -> 174
        const int nact  = 8 * units;
        const bool act  = tid < nact;
        const int u   = tid >> 3;                    // unit within CTA
        const int sub = tid & 7;                     // 2*gate + cc
        const int g   = sub >> 1;
        const int cc  = sub & 1;
        const int grow = act ? (g * HID + base + u) : 0;

        unsigned long long w[50];
        if (act) {
            const unsigned long long* wp =
                reinterpret_cast<const unsigned long long*>(W_hh + (size_t)grow * HID + cc * 100);
#pragma unroll
            for (int q = 0; q < 50; q++) w[q] = wp[q];
        }
        unsigned mask = 0;
        if (act) {
            int rem = nact - (tid & ~31);
            mask = (rem >= 32) ? 0xffffffffu : ((1u << rem) - 1u);
        }
        uint32_t r_h[CLSZ];
        if (act && sub == 0) {
            uint32_t hA = smem_u32(&S.h[0][0]);
#pragma unroll
            for (int p = 0; p < CLSZ; p++) r_h[p] = mapa_u32(hA, (uint32_t)p);
        }

        __syncthreads();
        cluster_sync_();   // h zeroed everywhere before any traffic

        float cst = 0.f;
        float gxv = (act && cc == 0) ? g_gx[grow] : 0.f;

        for (int t = 0; t < TSTEPS; t++) {
            const int buf = t & 1, bw = buf ^ 1;
            float gxn = 0.f;
            if (act && cc == 0) {
                int tn = (t + 1 < TSTEPS) ? (t + 1) : t;   // prefetch next gx
                gxn = g_gx[(size_t)tn * G4 + grow];
            }
            if (act) {
                const uint32_t haddr = smem_u32(&S.h[buf][0]) + (uint32_t)cc * 400u;
                unsigned long long a0 = 0, a1 = 0, a2 = 0, a3 = 0;
#pragma unroll
                for (int q = 0; q < 25; q++) {
                    unsigned long long x, y;
                    lds128(x, y, haddr + (uint32_t)q * 16u);
                    if (q & 1) { fma2(a2, w[2 * q], x); fma2(a3, w[2 * q + 1], y); }
                    else       { fma2(a0, w[2 * q], x); fma2(a1, w[2 * q + 1], y); }
                }
                float2 f0 = unpack2(a0), f1 = unpack2(a1), f2 = unpack2(a2), f3 = unpack2(a3);
                float dsum = ((f0.x + f0.y) + (f1.x + f1.y)) + ((f2.x + f2.y) + (f3.x + f3.y));
                dsum += __shfl_xor_sync(mask, dsum, 1);          // combine k-halves
                float av = 0.f;
                if (cc == 0) {
                    float gs = dsum + gxv;
                    av = (g == 2) ? ftanh(gs) : fsigmoid(gs);    // gate activation (even lanes)
                }
                float fv = __shfl_down_sync(mask, av, 2);
                float gv = __shfl_down_sync(mask, av, 4);
                float ov = __shfl_down_sync(mask, av, 6);
                if (sub == 0) {
                    cst = fv * cst + av * gv;
                    float h = ov * ftanh(cst);
                    const uint32_t off = (uint32_t)(bw * HID + base + u) * 4u;
#pragma unroll
                    for (int p = 0; p < CLSZ; p++) dsmem_st_f32(r_h[p] + off, h);
                }
            }
            gxv = gxn;
            cluster_sync_();       // release h_{t+1} writes; acquire for next step's reads
        }
        return;
    }

    // ================= consumer CTA =================
    unsigned long long wk[50];       // keys threads: WkT slice in registers
    if (tid >= 128 && tid < 208) {
        const int k = (tid - 128) >> 1, half = (tid - 128) & 1;
        const unsigned long long* wp =
            reinterpret_cast<const unsigned long long*>(g_WkT + k * HID + half * 100);
#pragma unroll
        for (int q = 0; q < 50; q++) wk[q] = wp[q];
    }
    unsigned long long M2[20];
    float wr = 0.f;
    for (int i = tid; i < HID; i += 256) S.Ws[i] = W_s[i];
    if (tid < KDIM) S.bk[tid] = b_k[tid];
    if (tid == 0)   S.bs = b_s[0];
    if (tid < NSLOT) {
#pragma unroll
        for (int q = 0; q < 20; q++) M2[q] = pack2(1e-6f, 1e-6f);
        wr = (tid == 0) ? 1.f : 0.f;
    }

    __syncthreads();
    cluster_sync_();   // h zeroed everywhere before any traffic

    for (int t = 0; t < TSTEPS; t++) {
        // keys(t-1) on warps 4-7 || MANN(t-2) on warps 0-3
        if (tid >= 128) {
            if (t >= 1) keys_sigma(S, tid, &S.h[t & 1][0], t & 1, wk);
        } else if (t >= 2) {
            mann_step(S, tid, (t - 1) & 1, M2, wr);
        }
        // cluster_sync doubles as the CTA-wide barrier (release/acquire, all threads)
        cluster_sync_();
    }

    // tail 1: keys for hiddens[4095] (in h[0]) || MANN for hiddens[4094] (key[1])
    if (tid >= 128) keys_sigma(S, tid, &S.h[0][0], 0, wk);
    else            mann_step(S, tid, 1, M2, wr);
    __syncthreads();
    // tail 2: MANN for hiddens[4095] (key[0])
    if (tid < 128)  mann_step(S, tid, 0, M2, wr);

    if (tid < NSLOT) {
#pragma unroll
        for (int q = 0; q < 20; q++) {
            float2 v = unpack2(M2[q]);
            out[tid * KDIM + 2 * q]     = v.x;
            out[tid * KDIM + 2 * q + 1] = v.y;
        }
    }
}

// ---------------- launch ----------------
extern "C" void kernel_launch(void* const* d_in, const int* in_sizes, int n_in,
                              void* d_out, int out_size) {
    const float* x    = (const float*)d_in[0];
    const float* y    = (const float*)d_in[1];
    const float* W_in = (const float*)d_in[2];
    const float* b_in = (const float*)d_in[3];
    const float* W_ih = (const float*)d_in[4];
    const float* W_hh = (const float*)d_in[5];
    const float* b_ih = (const float*)d_in[6];
    const float* b_hh = (const float*)d_in[7];
    const float* W_k  = (const float*)d_in[8];
    const float* b_k  = (const float*)d_in[9];
    const float* W_s  = (const float*)d_in[10];
    const float* b_s  = (const float*)d_in[11];
    // gamma (d_in[12]) provably unused: wlu mask is identically 1, wu/gamma cancel

    prep_kernel<<<(G4 * FDIM + 255) / 256, 256>>>(W_in, W_ih, b_ih, b_hh, W_k);
    gemm1_kernel<<<dim3(FDIM / 64, TSTEPS / 64), 256>>>(x, b_in);
    gemm2_kernel<<<dim3((G4 + 63) / 64, TSTEPS / 64), 256>>>(y);
    fused_kernel<<<CLSZ, 256>>>(W_hh, b_k, W_s, b_s, (float*)d_out);
}